// round 16
// baseline (speedup 1.0000x reference)
#include <cuda_runtime.h>
#include <cstdint>

#define Bn 2
#define Nn 6
#define Dn 59
#define FHn 16
#define FWn 44
#define Cn 80
#define Xn 256
#define Yn 256

#define PSPLIT 4   // pool feature-loop split factor

// scratch layout: [b][y][x][c], c contiguous; 16B-aligned for red.v4.
// INVARIANT: all-zero at every kernel_launch exit (globals start zeroed;
// transpose phase-2 re-zeroes its slice each launch) -> graph-replay safe.
__device__ __align__(256) float g_scratch[(size_t)Bn * Yn * Xn * Cn];

__device__ __forceinline__ void red_add_v4(float* ptr, float4 v) {
    asm volatile("red.global.add.v4.f32 [%0], {%1, %2, %3, %4};"
                 :: "l"(ptr), "f"(v.x), "f"(v.y), "f"(v.z), "f"(v.w)
                 : "memory");
}

// streaming (evict-first) float4 load — x has zero reuse, keep it out of L2
__device__ __forceinline__ float4 ldcs_v4(const float* p) {
    return __ldcs(reinterpret_cast<const float4*>(p));
}

// XLA strength-reduced dot: mul, mul, mul, add left-to-right. (FROZEN)
__device__ __forceinline__ float dot3m(float m0, float m1, float m2,
                                       float v0, float v1, float v2) {
    float p0 = __fmul_rn(m0, v0);
    float p1 = __fmul_rn(m1, v1);
    float p2 = __fmul_rn(m2, v2);
    return __fadd_rn(__fadd_rn(p0, p1), p2);
}

// adjugate inverse in fp32 — exact on identity (dataset post_rots / l2e_rots)
__device__ __forceinline__ void inv3_adj(const float* m, float* o) {
    float a = m[0], b = m[1], c = m[2];
    float d = m[3], e = m[4], f = m[5];
    float g = m[6], h = m[7], i = m[8];
    float A  = __fadd_rn(__fmul_rn(e, i), -__fmul_rn(f, h));
    float Bc = -__fadd_rn(__fmul_rn(d, i), -__fmul_rn(f, g));
    float Cc = __fadd_rn(__fmul_rn(d, h), -__fmul_rn(e, g));
    float det = __fadd_rn(__fadd_rn(__fmul_rn(a, A), __fmul_rn(b, Bc)), __fmul_rn(c, Cc));
    float r = __fdiv_rn(1.0f, det);
    o[0] = __fmul_rn(A, r);
    o[1] = __fmul_rn(__fadd_rn(__fmul_rn(c, h), -__fmul_rn(b, i)), r);
    o[2] = __fmul_rn(__fadd_rn(__fmul_rn(b, f), -__fmul_rn(c, e)), r);
    o[3] = __fmul_rn(Bc, r);
    o[4] = __fmul_rn(__fadd_rn(__fmul_rn(a, i), -__fmul_rn(c, g)), r);
    o[5] = __fmul_rn(__fadd_rn(__fmul_rn(c, d), -__fmul_rn(a, f)), r);
    o[6] = __fmul_rn(Cc, r);
    o[7] = __fmul_rn(__fadd_rn(__fmul_rn(b, g), -__fmul_rn(a, h)), r);
    o[8] = __fmul_rn(__fadd_rn(__fmul_rn(a, e), -__fmul_rn(b, d)), r);
}

// LAPACK strti2-style upper-triangular fp32 inverse  (FROZEN)
__device__ __forceinline__ void inv3_lapack_tri(const float* m, float* o) {
    float A01 = m[1], A02 = m[2], A12 = m[5];
    float i00 = __fdiv_rn(1.0f, m[0]);
    float i11 = __fdiv_rn(1.0f, m[4]);
    float i22 = __fdiv_rn(1.0f, m[8]);
    float x0c1 = __fmul_rn(A01, i00);
    float i01 = -__fmul_rn(i11, x0c1);
    float x0 = __fmul_rn(A02, i00);
    x0 = __fadd_rn(x0, __fmul_rn(A12, i01));
    float x1 = __fmul_rn(A12, i11);
    float i02 = -__fmul_rn(i22, x0);
    float i12 = -__fmul_rn(i22, x1);
    o[0] = i00; o[1] = i01; o[2] = i02;
    o[3] = 0.f; o[4] = i11; o[5] = i12;
    o[6] = 0.f; o[7] = 0.f; o[8] = i22;
}

// PSPLIT blocks per (b,n,w) ray-bundle; 256 threads each. h rows share the
// BEV voxel (verified dynamically) -> presum over h, ONE v4-RED per (d,c4).
// Each block takes an interleaved 1/PSPLIT of the (k,c4) feature work.
// Compaction is DETERMINISTIC (ascending d, flag+count, no atomics) so all
// sibling blocks agree on the k -> depth mapping.
__global__ void pool_kernel(const float* __restrict__ x,
                            const float* __restrict__ rots,
                            const float* __restrict__ trans,
                            const float* __restrict__ intrins,
                            const float* __restrict__ post_rots,
                            const float* __restrict__ post_trans,
                            const float* __restrict__ l2e_rots,
                            const float* __restrict__ l2e_trans) {
    int part = blockIdx.x & (PSPLIT - 1);
    int col  = blockIdx.x >> 2;           // 0 .. Bn*Nn*FWn-1  (PSPLIT==4)
    int w = col % FWn; int t1 = col / FWn;
    int n = t1 % Nn;   int b = t1 / Nn;

    __shared__ float sA[9];
    __shared__ float sC[9];
    __shared__ float sIL[9];
    __shared__ float sTr[3];
    __shared__ float sLT[3];
    __shared__ float sPT[3];
    __shared__ int   s_vox[FHn * Dn];
    __shared__ int   s_dmask[Dn];         // per-depth kept-h bitmask
    __shared__ int   s_dvox[Dn];          // per-depth common voxel
    __shared__ int   s_duni[Dn];          // per-depth uniformity
    __shared__ int   s_ld[Dn];            // compacted depth list (ascending d)
    __shared__ int   s_cnt;

    if (threadIdx.x == 0) {
        int bn = b * Nn + n;
        float invI[9];
        inv3_adj(post_rots + bn * 9, sA);
        inv3_lapack_tri(intrins + bn * 9, invI);
        inv3_adj(l2e_rots + b * 9, sIL);
        const float* R = rots + bn * 9;
        #pragma unroll
        for (int r = 0; r < 3; r++)
            #pragma unroll
            for (int c = 0; c < 3; c++)
                sC[r * 3 + c] = dot3m(R[r * 3 + 0], R[r * 3 + 1], R[r * 3 + 2],
                                      invI[0 * 3 + c], invI[1 * 3 + c], invI[2 * 3 + c]);
        #pragma unroll
        for (int k = 0; k < 3; k++) {
            sTr[k] = trans[bn * 3 + k];
            sLT[k] = l2e_trans[b * 3 + k];
            sPT[k] = post_trans[bn * 3 + k];
        }
    }
    __syncthreads();

    // ===== FROZEN geometry chain, one thread-iteration per (h,d) point =====
    for (int idx = threadIdx.x; idx < FHn * Dn; idx += blockDim.x) {
        int h = idx / Dn;
        int d = idx - h * Dn;
        float ustep = __fdiv_rn(703.0f, 43.0f);
        float vstep = __fdiv_rn(255.0f, 15.0f);
        float u = __fmul_rn((float)w, ustep);
        float v = __fmul_rn((float)h, vstep);
        float dep = (float)(d + 1);
        float f0 = __fadd_rn(u, -sPT[0]);
        float f1 = __fadd_rn(v, -sPT[1]);
        float f2 = __fadd_rn(dep, -sPT[2]);
        float p1x = dot3m(sA[0], sA[1], sA[2], f0, f1, f2);
        float p1y = dot3m(sA[3], sA[4], sA[5], f0, f1, f2);
        float p1z = dot3m(sA[6], sA[7], sA[8], f0, f1, f2);
        float p2x = __fmul_rn(p1x, p1z);
        float p2y = __fmul_rn(p1y, p1z);
        float p2z = p1z;
        float e0 = __fadd_rn(dot3m(sC[0], sC[1], sC[2], p2x, p2y, p2z), sTr[0]);
        float e1 = __fadd_rn(dot3m(sC[3], sC[4], sC[5], p2x, p2y, p2z), sTr[1]);
        float e2 = __fadd_rn(dot3m(sC[6], sC[7], sC[8], p2x, p2y, p2z), sTr[2]);
        e0 = __fadd_rn(e0, -sLT[0]);
        e1 = __fadd_rn(e1, -sLT[1]);
        e2 = __fadd_rn(e2, -sLT[2]);
        float gx = dot3m(sIL[0], sIL[1], sIL[2], e0, e1, e2);
        float gy = dot3m(sIL[3], sIL[4], sIL[5], e0, e1, e2);
        float gz = dot3m(sIL[6], sIL[7], sIL[8], e0, e1, e2);
        // div-by-const -> mul-by-recip (fl32(1/0.4f)==2.5f, fl32(1/8f)==0.125f)
        float oxy = __fadd_rn(-51.0f, -__fmul_rn(0.4f, 0.5f));
        float ozz = __fadd_rn(-1.0f, -__fmul_rn(8.0f, 0.5f));
        int c0 = (int)__fmul_rn(__fadd_rn(gx, -oxy), 2.5f);
        int c1 = (int)__fmul_rn(__fadd_rn(gy, -oxy), 2.5f);
        int c2 = (int)__fmul_rn(__fadd_rn(gz, -ozz), 0.125f);
        bool kept = (c0 >= 0) && (c0 < Xn) && (c1 >= 0) && (c1 < Yn) && (c2 == 0);
        s_vox[idx] = kept ? ((((b * Yn) + c1) * Xn + c0) * Cn) : -1;
    }
    __syncthreads();

    // per-depth metadata (flags; deterministic, no atomics)
    if (threadIdx.x < Dn) {
        int d = threadIdx.x;
        int mask = 0, vox = -1, uni = 1;
        #pragma unroll
        for (int h = 0; h < FHn; h++) {
            int vv = s_vox[h * Dn + d];
            if (vv >= 0) {
                if (vox < 0) vox = vv;
                else if (vv != vox) uni = 0;
                mask |= (1 << h);
            }
        }
        s_dmask[d] = mask; s_dvox[d] = vox; s_duni[d] = uni;
    }
    __syncthreads();

    // deterministic compaction: slot = #kept depths below d (ascending order)
    if (threadIdx.x < Dn) {
        int d = threadIdx.x;
        if (s_dmask[d]) {
            int pos = 0;
            for (int dd = 0; dd < d; dd++) pos += (s_dmask[dd] != 0);
            s_ld[pos] = d;
        }
        if (d == Dn - 1) {
            int c = 0;
            for (int dd = 0; dd < Dn; dd++) c += (s_dmask[dd] != 0);
            s_cnt = c;
        }
    }
    __syncthreads();

    int cnt = s_cnt;
    if (cnt == 0) return;

    // x layout: [B][N][D][FH][FW][C]
    const size_t base_bnw = ((size_t)(b * Nn + n) * Dn * FHn * FWn) * Cn
                          + (size_t)w * Cn;
    const size_t dstride = (size_t)FHn * FWn * Cn;
    const size_t hstride = (size_t)FWn * Cn;

    // flat (k, c4) work, interleaved across PSPLIT blocks; identical s_ld
    // across sibling blocks => exact partition of (depth, c4) work items.
    const int nwork = cnt * 20;
    for (int i = threadIdx.x + part * 256; i < nwork; i += 256 * PSPLIT) {
        int k  = i / 20;
        int c4 = (i - k * 20) * 4;
        int d    = s_ld[k];
        int mask = s_dmask[d];
        const float* px = x + base_bnw + (size_t)d * dstride + c4;
        if (s_duni[d]) {
            float4 acc = make_float4(0.f, 0.f, 0.f, 0.f);
            #pragma unroll
            for (int h = 0; h < FHn; h++) {
                if (mask & (1 << h)) {
                    float4 v = ldcs_v4(px + (size_t)h * hstride);
                    acc.x += v.x; acc.y += v.y; acc.z += v.z; acc.w += v.w;
                }
            }
            red_add_v4(&g_scratch[(size_t)s_dvox[d] + c4], acc);
        } else {
            #pragma unroll
            for (int h = 0; h < FHn; h++) {
                if (mask & (1 << h)) {
                    float4 v = ldcs_v4(px + (size_t)h * hstride);
                    red_add_v4(&g_scratch[(size_t)s_vox[h * Dn + d] + c4], v);
                }
            }
        }
    }
}

// transpose scratch [b][y][x][c] -> out [b][c][y][x]; one block per
// (b, y, x-eighth=32 cols). 11.5 KB tile -> high occupancy for miss latency
// hiding. Phase 1: read slice into smem. Phase 2: zero slice (replaces the
// standalone zero kernel; leaves scratch warm-zero for next replay).
// Phase 3: vectorized permuted stores (LDS.128 + STG.128).
#define TSTRIDE 36   // 32 + 4: multiple of 4 (16B-aligned rows for LDS.128)
__global__ void transpose_kernel(float* __restrict__ out) {
    int blk = blockIdx.x;                  // 0 .. Bn*Yn*8-1
    int xo = blk & 7;
    int y = (blk >> 3) & (Yn - 1);
    int b = blk >> 11;

    __shared__ float tile[Cn * TSTRIDE];   // [c][xl], xl in 0..31

    float* src = g_scratch
        + (((size_t)(b * Yn + y) * Xn) + (size_t)xo * 32) * Cn;

    // phase 1: read 32*80 = 2560 floats + transpose-scatter into smem
    #pragma unroll
    for (int it = 0; it < 10; it++) {
        int i  = threadIdx.x + it * 256;   // 0 .. 2559
        int xl = i / Cn;
        int c  = i - xl * Cn;
        tile[c * TSTRIDE + xl] = src[i];
    }
    __syncthreads();

    // phase 2: zero the slice (640 float4 stores; L2-absorbed)
    {
        const float4 z4 = make_float4(0.f, 0.f, 0.f, 0.f);
        float4* s4 = reinterpret_cast<float4*>(src);
        #pragma unroll
        for (int it = 0; it < 3; it++) {
            int i = threadIdx.x + it * 256;
            if (i < 640) s4[i] = z4;
        }
    }

    // phase 3: 640 float4 stores; 8 threads cover one c-row (128B contig)
    #pragma unroll
    for (int it = 0; it < 3; it++) {
        int i  = threadIdx.x + it * 256;   // 0 .. 639
        if (i < 640) {
            int c  = i >> 3;
            int x4 = (i & 7) << 2;
            float4 v = *reinterpret_cast<const float4*>(&tile[c * TSTRIDE + x4]);
            size_t dst = (((size_t)(b * Cn + c) * Yn + y) << 8)
                       + (size_t)xo * 32 + x4;
            *reinterpret_cast<float4*>(&out[dst]) = v;
        }
    }
}

extern "C" void kernel_launch(void* const* d_in, const int* in_sizes, int n_in,
                              void* d_out, int out_size) {
    const float* x          = (const float*)d_in[0];
    const float* rots       = (const float*)d_in[1];
    const float* trans      = (const float*)d_in[2];
    const float* intrins    = (const float*)d_in[3];
    const float* post_rots  = (const float*)d_in[4];
    const float* post_trans = (const float*)d_in[5];
    const float* l2e_rots   = (const float*)d_in[6];
    const float* l2e_trans  = (const float*)d_in[7];
    float* out = (float*)d_out;

    pool_kernel<<<Bn * Nn * FWn * PSPLIT, 256>>>(x, rots, trans, intrins,
                                                 post_rots, post_trans,
                                                 l2e_rots, l2e_trans);

    transpose_kernel<<<Bn * Yn * 8, 256>>>(out);
}

// round 17
// speedup vs baseline: 1.2290x; 1.2290x over previous
#include <cuda_runtime.h>
#include <cstdint>

#define Bn 2
#define Nn 6
#define Dn 59
#define FHn 16
#define FWn 44
#define Cn 80
#define Xn 256
#define Yn 256

// scratch layout: [b][y][x][c], c contiguous; 16B-aligned for red.v4.
// INVARIANT: all-zero at every kernel_launch exit (globals start zeroed;
// transpose phase-2 re-zeroes its slice each launch) -> graph-replay safe.
__device__ __align__(256) float g_scratch[(size_t)Bn * Yn * Xn * Cn];

__device__ __forceinline__ void red_add_v4(float* ptr, float4 v) {
    asm volatile("red.global.add.v4.f32 [%0], {%1, %2, %3, %4};"
                 :: "l"(ptr), "f"(v.x), "f"(v.y), "f"(v.z), "f"(v.w)
                 : "memory");
}

// streaming (evict-first) float4 load — x has zero reuse, keep it out of L2
__device__ __forceinline__ float4 ldcs_v4(const float* p) {
    return __ldcs(reinterpret_cast<const float4*>(p));
}

// XLA strength-reduced dot: mul, mul, mul, add left-to-right. (FROZEN)
__device__ __forceinline__ float dot3m(float m0, float m1, float m2,
                                       float v0, float v1, float v2) {
    float p0 = __fmul_rn(m0, v0);
    float p1 = __fmul_rn(m1, v1);
    float p2 = __fmul_rn(m2, v2);
    return __fadd_rn(__fadd_rn(p0, p1), p2);
}

// adjugate inverse in fp32 — exact on identity (dataset post_rots / l2e_rots)
__device__ __forceinline__ void inv3_adj(const float* m, float* o) {
    float a = m[0], b = m[1], c = m[2];
    float d = m[3], e = m[4], f = m[5];
    float g = m[6], h = m[7], i = m[8];
    float A  = __fadd_rn(__fmul_rn(e, i), -__fmul_rn(f, h));
    float Bc = -__fadd_rn(__fmul_rn(d, i), -__fmul_rn(f, g));
    float Cc = __fadd_rn(__fmul_rn(d, h), -__fmul_rn(e, g));
    float det = __fadd_rn(__fadd_rn(__fmul_rn(a, A), __fmul_rn(b, Bc)), __fmul_rn(c, Cc));
    float r = __fdiv_rn(1.0f, det);
    o[0] = __fmul_rn(A, r);
    o[1] = __fmul_rn(__fadd_rn(__fmul_rn(c, h), -__fmul_rn(b, i)), r);
    o[2] = __fmul_rn(__fadd_rn(__fmul_rn(b, f), -__fmul_rn(c, e)), r);
    o[3] = __fmul_rn(Bc, r);
    o[4] = __fmul_rn(__fadd_rn(__fmul_rn(a, i), -__fmul_rn(c, g)), r);
    o[5] = __fmul_rn(__fadd_rn(__fmul_rn(c, d), -__fmul_rn(a, f)), r);
    o[6] = __fmul_rn(Cc, r);
    o[7] = __fmul_rn(__fadd_rn(__fmul_rn(b, g), -__fmul_rn(a, h)), r);
    o[8] = __fmul_rn(__fadd_rn(__fmul_rn(a, e), -__fmul_rn(b, d)), r);
}

// LAPACK strti2-style upper-triangular fp32 inverse  (FROZEN)
__device__ __forceinline__ void inv3_lapack_tri(const float* m, float* o) {
    float A01 = m[1], A02 = m[2], A12 = m[5];
    float i00 = __fdiv_rn(1.0f, m[0]);
    float i11 = __fdiv_rn(1.0f, m[4]);
    float i22 = __fdiv_rn(1.0f, m[8]);
    float x0c1 = __fmul_rn(A01, i00);
    float i01 = -__fmul_rn(i11, x0c1);
    float x0 = __fmul_rn(A02, i00);
    x0 = __fadd_rn(x0, __fmul_rn(A12, i01));
    float x1 = __fmul_rn(A12, i11);
    float i02 = -__fmul_rn(i22, x0);
    float i12 = -__fmul_rn(i22, x1);
    o[0] = i00; o[1] = i01; o[2] = i02;
    o[3] = 0.f; o[4] = i11; o[5] = i12;
    o[6] = 0.f; o[7] = 0.f; o[8] = i22;
}

// one block per (b,n,w) ray-bundle; 256 threads. h rows share the BEV voxel
// (verified dynamically) -> presum over h, ONE v4-RED per (d,c4).
__global__ void pool_kernel(const float* __restrict__ x,
                            const float* __restrict__ rots,
                            const float* __restrict__ trans,
                            const float* __restrict__ intrins,
                            const float* __restrict__ post_rots,
                            const float* __restrict__ post_trans,
                            const float* __restrict__ l2e_rots,
                            const float* __restrict__ l2e_trans) {
    int col = blockIdx.x;                 // 0 .. Bn*Nn*FWn-1
    int w = col % FWn; int t1 = col / FWn;
    int n = t1 % Nn;   int b = t1 / Nn;

    __shared__ float sA[9];
    __shared__ float sC[9];
    __shared__ float sIL[9];
    __shared__ float sTr[3];
    __shared__ float sLT[3];
    __shared__ float sPT[3];
    __shared__ int   s_vox[FHn * Dn];
    __shared__ int   s_dmask[Dn];         // per-depth kept-h bitmask
    __shared__ int   s_dvox[Dn];          // per-depth common voxel
    __shared__ int   s_duni[Dn];          // per-depth uniformity
    __shared__ int   s_ld[Dn];            // compacted depth list (ascending d)
    __shared__ int   s_cnt;

    if (threadIdx.x == 0) {
        int bn = b * Nn + n;
        float invI[9];
        inv3_adj(post_rots + bn * 9, sA);
        inv3_lapack_tri(intrins + bn * 9, invI);
        inv3_adj(l2e_rots + b * 9, sIL);
        const float* R = rots + bn * 9;
        #pragma unroll
        for (int r = 0; r < 3; r++)
            #pragma unroll
            for (int c = 0; c < 3; c++)
                sC[r * 3 + c] = dot3m(R[r * 3 + 0], R[r * 3 + 1], R[r * 3 + 2],
                                      invI[0 * 3 + c], invI[1 * 3 + c], invI[2 * 3 + c]);
        #pragma unroll
        for (int k = 0; k < 3; k++) {
            sTr[k] = trans[bn * 3 + k];
            sLT[k] = l2e_trans[b * 3 + k];
            sPT[k] = post_trans[bn * 3 + k];
        }
    }
    __syncthreads();

    // ===== FROZEN geometry chain, one thread-iteration per (h,d) point =====
    for (int idx = threadIdx.x; idx < FHn * Dn; idx += blockDim.x) {
        int h = idx / Dn;
        int d = idx - h * Dn;
        float ustep = __fdiv_rn(703.0f, 43.0f);
        float vstep = __fdiv_rn(255.0f, 15.0f);
        float u = __fmul_rn((float)w, ustep);
        float v = __fmul_rn((float)h, vstep);
        float dep = (float)(d + 1);
        float f0 = __fadd_rn(u, -sPT[0]);
        float f1 = __fadd_rn(v, -sPT[1]);
        float f2 = __fadd_rn(dep, -sPT[2]);
        float p1x = dot3m(sA[0], sA[1], sA[2], f0, f1, f2);
        float p1y = dot3m(sA[3], sA[4], sA[5], f0, f1, f2);
        float p1z = dot3m(sA[6], sA[7], sA[8], f0, f1, f2);
        float p2x = __fmul_rn(p1x, p1z);
        float p2y = __fmul_rn(p1y, p1z);
        float p2z = p1z;
        float e0 = __fadd_rn(dot3m(sC[0], sC[1], sC[2], p2x, p2y, p2z), sTr[0]);
        float e1 = __fadd_rn(dot3m(sC[3], sC[4], sC[5], p2x, p2y, p2z), sTr[1]);
        float e2 = __fadd_rn(dot3m(sC[6], sC[7], sC[8], p2x, p2y, p2z), sTr[2]);
        e0 = __fadd_rn(e0, -sLT[0]);
        e1 = __fadd_rn(e1, -sLT[1]);
        e2 = __fadd_rn(e2, -sLT[2]);
        float gx = dot3m(sIL[0], sIL[1], sIL[2], e0, e1, e2);
        float gy = dot3m(sIL[3], sIL[4], sIL[5], e0, e1, e2);
        float gz = dot3m(sIL[6], sIL[7], sIL[8], e0, e1, e2);
        // div-by-const -> mul-by-recip (fl32(1/0.4f)==2.5f, fl32(1/8f)==0.125f)
        float oxy = __fadd_rn(-51.0f, -__fmul_rn(0.4f, 0.5f));
        float ozz = __fadd_rn(-1.0f, -__fmul_rn(8.0f, 0.5f));
        int c0 = (int)__fmul_rn(__fadd_rn(gx, -oxy), 2.5f);
        int c1 = (int)__fmul_rn(__fadd_rn(gy, -oxy), 2.5f);
        int c2 = (int)__fmul_rn(__fadd_rn(gz, -ozz), 0.125f);
        bool kept = (c0 >= 0) && (c0 < Xn) && (c1 >= 0) && (c1 < Yn) && (c2 == 0);
        s_vox[idx] = kept ? ((((b * Yn) + c1) * Xn + c0) * Cn) : -1;
    }
    __syncthreads();

    // per-depth metadata (flags; deterministic, no atomics)
    if (threadIdx.x < Dn) {
        int d = threadIdx.x;
        int mask = 0, vox = -1, uni = 1;
        #pragma unroll
        for (int h = 0; h < FHn; h++) {
            int vv = s_vox[h * Dn + d];
            if (vv >= 0) {
                if (vox < 0) vox = vv;
                else if (vv != vox) uni = 0;
                mask |= (1 << h);
            }
        }
        s_dmask[d] = mask; s_dvox[d] = vox; s_duni[d] = uni;
    }
    __syncthreads();

    // deterministic compaction: slot = #kept depths below d (ascending order)
    if (threadIdx.x < Dn) {
        int d = threadIdx.x;
        if (s_dmask[d]) {
            int pos = 0;
            for (int dd = 0; dd < d; dd++) pos += (s_dmask[dd] != 0);
            s_ld[pos] = d;
        }
        if (d == Dn - 1) {
            int c = 0;
            for (int dd = 0; dd < Dn; dd++) c += (s_dmask[dd] != 0);
            s_cnt = c;
        }
    }
    __syncthreads();

    int cnt = s_cnt;
    if (cnt == 0) return;

    // x layout: [B][N][D][FH][FW][C]
    const size_t base_bnw = ((size_t)(b * Nn + n) * Dn * FHn * FWn) * Cn
                          + (size_t)w * Cn;
    const size_t dstride = (size_t)FHn * FWn * Cn;
    const size_t hstride = (size_t)FWn * Cn;

    // flat (k, c4) work distribution over all 256 threads
    const int nwork = cnt * 20;
    for (int i = threadIdx.x; i < nwork; i += 256) {
        int k  = i / 20;
        int c4 = (i - k * 20) * 4;
        int d    = s_ld[k];
        int mask = s_dmask[d];
        const float* px = x + base_bnw + (size_t)d * dstride + c4;
        if (s_duni[d]) {
            float4 acc = make_float4(0.f, 0.f, 0.f, 0.f);
            #pragma unroll
            for (int h = 0; h < FHn; h++) {
                if (mask & (1 << h)) {
                    float4 v = ldcs_v4(px + (size_t)h * hstride);
                    acc.x += v.x; acc.y += v.y; acc.z += v.z; acc.w += v.w;
                }
            }
            red_add_v4(&g_scratch[(size_t)s_dvox[d] + c4], acc);
        } else {
            #pragma unroll
            for (int h = 0; h < FHn; h++) {
                if (mask & (1 << h)) {
                    float4 v = ldcs_v4(px + (size_t)h * hstride);
                    red_add_v4(&g_scratch[(size_t)s_vox[h * Dn + d] + c4], v);
                }
            }
        }
    }
}

// transpose scratch [b][y][x][c] -> out [b][c][y][x]; one block per
// (b, y, x-eighth=32 cols). Phase 1: read slice into smem (should hit L2 —
// scratch lines stay resident across replays because out stores are
// streaming). Phase 2: zero slice (replaces standalone zero kernel; leaves
// scratch warm-zero in L2 for next replay). Phase 3: vectorized permuted
// stores with st.global.cs (evict-first: out is never re-read; do NOT let
// 42 MB of out writes evict scratch from L2).
#define TSTRIDE 36   // 32 + 4: multiple of 4 (16B-aligned rows for LDS.128)
__global__ void transpose_kernel(float* __restrict__ out) {
    int blk = blockIdx.x;                  // 0 .. Bn*Yn*8-1
    int xo = blk & 7;
    int y = (blk >> 3) & (Yn - 1);
    int b = blk >> 11;

    __shared__ float tile[Cn * TSTRIDE];   // [c][xl], xl in 0..31

    float* src = g_scratch
        + (((size_t)(b * Yn + y) * Xn) + (size_t)xo * 32) * Cn;

    // phase 1: read 32*80 = 2560 floats + transpose-scatter into smem
    #pragma unroll
    for (int it = 0; it < 10; it++) {
        int i  = threadIdx.x + it * 256;   // 0 .. 2559
        int xl = i / Cn;
        int c  = i - xl * Cn;
        tile[c * TSTRIDE + xl] = src[i];
    }
    __syncthreads();

    // phase 2: zero the slice (640 float4 stores; default policy — keep
    // these lines RESIDENT in L2 for the next replay's pool/transpose)
    {
        const float4 z4 = make_float4(0.f, 0.f, 0.f, 0.f);
        float4* s4 = reinterpret_cast<float4*>(src);
        #pragma unroll
        for (int it = 0; it < 3; it++) {
            int i = threadIdx.x + it * 256;
            if (i < 640) s4[i] = z4;
        }
    }

    // phase 3: 640 float4 streaming stores; 8 threads per c-row (128B contig)
    #pragma unroll
    for (int it = 0; it < 3; it++) {
        int i  = threadIdx.x + it * 256;   // 0 .. 639
        if (i < 640) {
            int c  = i >> 3;
            int x4 = (i & 7) << 2;
            float4 v = *reinterpret_cast<const float4*>(&tile[c * TSTRIDE + x4]);
            size_t dst = (((size_t)(b * Cn + c) * Yn + y) << 8)
                       + (size_t)xo * 32 + x4;
            __stcs(reinterpret_cast<float4*>(&out[dst]), v);
        }
    }
}

extern "C" void kernel_launch(void* const* d_in, const int* in_sizes, int n_in,
                              void* d_out, int out_size) {
    const float* x          = (const float*)d_in[0];
    const float* rots       = (const float*)d_in[1];
    const float* trans      = (const float*)d_in[2];
    const float* intrins    = (const float*)d_in[3];
    const float* post_rots  = (const float*)d_in[4];
    const float* post_trans = (const float*)d_in[5];
    const float* l2e_rots   = (const float*)d_in[6];
    const float* l2e_trans  = (const float*)d_in[7];
    float* out = (float*)d_out;

    pool_kernel<<<Bn * Nn * FWn, 256>>>(x, rots, trans, intrins, post_rots,
                                        post_trans, l2e_rots, l2e_trans);

    transpose_kernel<<<Bn * Yn * 8, 256>>>(out);
}